// round 3
// baseline (speedup 1.0000x reference)
#include <cuda_runtime.h>
#include <cstdint>
#include <cstddef>

#define N_NODES 32768
#define N_EDGES 524288

// ---- scratch (device globals; allocations forbidden) ----
__device__ float g_x[(size_t)N_NODES * 256];   // [0:64]=x0, [64+u*3+i]=x1[u][i]
__device__ float g_m[(size_t)N_NODES * 512];   // [0:128]=m0, [128+v*3+i]=m1[v][i]
__device__ float g_wt0[640 * 64];              // W_skip0^T: [(v*10+w)*64 + u]
__device__ float g_wt1[640 * 64];

#define C_UP      0.125f
#define C_R1      0.35355339059327373f
#define C_R       0.125f
#define C_LIN     0.00552427172801990f
#define C_SKIP    0.03952847075210474f
#define INV_SQRT3 0.5773502691896258f

__device__ __forceinline__ float silu_f(float x) {
    return __fdividef(x, 1.0f + __expf(-x));
}
__device__ __forceinline__ void red_add_v4(float* a, float x, float y, float z, float w) {
    asm volatile("red.global.add.v4.f32 [%0], {%1,%2,%3,%4};"
                 :: "l"(a), "f"(x), "f"(y), "f"(z), "f"(w) : "memory");
}

// ==== K_prep: W_skip (64,64,10)[u,v,w] -> [(v*10+w), u] ====
__global__ void k_prep(const float* __restrict__ Ws0, const float* __restrict__ Ws1) {
    int vw = blockIdx.x, u = threadIdx.x;
    g_wt0[vw * 64 + u] = Ws0[u * 640 + vw];
    g_wt1[vw * 64 + u] = Ws1[u * 640 + vw];
}

// ==== K0: node up-projection (8 nodes/block) ====
__global__ __launch_bounds__(256) void k_node_up(const float* __restrict__ nf,
                                                 const float* __restrict__ Wu0,
                                                 const float* __restrict__ Wu1) {
    __shared__ float sW0[4096], sW1[4096], sIn[2048];
    const int t = threadIdx.x;
    for (int i = t; i < 4096; i += 256) { sW0[i] = Wu0[i]; sW1[i] = Wu1[i]; }
    const int n0 = blockIdx.x * 8;
    for (int i = t; i < 2048; i += 256) sIn[i] = nf[(size_t)n0 * 256 + i];
    __syncthreads();
    const int j = t >> 6, u = t & 63;
    const int off0 = (j == 0) ? 0 : (63 + j);
    const int st = (j == 0) ? 1 : 3;
    const float* W = (j == 0) ? sW0 : sW1;
    const int oo = (j == 0) ? u : (64 + u * 3 + (j - 1));
    for (int c = 0; c < 2; c++) {
        float acc[4] = {0.f, 0.f, 0.f, 0.f};
        #pragma unroll 8
        for (int v = 0; v < 64; v++) {
            float w = W[v * 64 + u];
            #pragma unroll
            for (int r = 0; r < 4; r++)
                acc[r] += sIn[(c * 4 + r) * 256 + off0 + v * st] * w;
        }
        #pragma unroll
        for (int r = 0; r < 4; r++)
            g_x[(size_t)(n0 + c * 4 + r) * 256 + oo] = acc[r] * C_UP;
    }
}

// ==== K1: persistent edge kernel, 64 edges/tile ====
#define ST_H   68
#define ST_TPW 260
#define OFF_WR1 0
#define OFF_WR2 512
#define OFF_WR3 4608
#define OFF_WR4 8704
#define OFF_HA  25088
#define OFF_HB  (OFF_HA + 64*ST_H)
#define OFF_TPW (OFF_HB + 64*ST_H)
#define OFF_EF  (OFF_TPW + 64*ST_TPW)
#define OFF_EA  (OFF_EF + 512)
#define OFF_SRC (OFF_EA + 256)
#define OFF_DST (OFF_SRC + 64)
#define K1_SMEM_FLOATS (OFF_DST + 64)

template<int K, int BSTRIDE, bool SILU>
__device__ __forceinline__ void gemm_tile(const float* __restrict__ A, int astride,
                                          const float* __restrict__ B, int bcol,
                                          float* __restrict__ O, int ostride, int ocol,
                                          float scale, int e0l, int e1l, int cb) {
    float acc[2][8];
    #pragma unroll
    for (int r = 0; r < 2; r++)
        #pragma unroll
        for (int j = 0; j < 8; j++) acc[r][j] = 0.f;
    const int bc = bcol + cb;
    #pragma unroll 8
    for (int k = 0; k < K; k++) {
        float a0 = A[e0l * astride + k];
        float a1 = A[e1l * astride + k];
        const float4 b0 = *(const float4*)(B + k * BSTRIDE + bc);
        const float4 b1 = *(const float4*)(B + k * BSTRIDE + bc + 4);
        acc[0][0] += a0*b0.x; acc[0][1] += a0*b0.y; acc[0][2] += a0*b0.z; acc[0][3] += a0*b0.w;
        acc[0][4] += a0*b1.x; acc[0][5] += a0*b1.y; acc[0][6] += a0*b1.z; acc[0][7] += a0*b1.w;
        acc[1][0] += a1*b0.x; acc[1][1] += a1*b0.y; acc[1][2] += a1*b0.z; acc[1][3] += a1*b0.w;
        acc[1][4] += a1*b1.x; acc[1][5] += a1*b1.y; acc[1][6] += a1*b1.z; acc[1][7] += a1*b1.w;
    }
    #pragma unroll
    for (int r = 0; r < 2; r++) {
        const int e = r ? e1l : e0l;
        float v[8];
        #pragma unroll
        for (int j = 0; j < 8; j++) {
            float x = acc[r][j] * scale;
            v[j] = SILU ? silu_f(x) : x;
        }
        float* op = O + e * ostride + ocol + cb;
        *(float4*)(op)     = make_float4(v[0], v[1], v[2], v[3]);
        *(float4*)(op + 4) = make_float4(v[4], v[5], v[6], v[7]);
    }
}

__global__ __launch_bounds__(256, 1) void k_edge(const float* __restrict__ ef,
                                                 const float* __restrict__ ea,
                                                 const int* __restrict__ src,
                                                 const int* __restrict__ dst,
                                                 const float* __restrict__ Wr1,
                                                 const float* __restrict__ Wr2,
                                                 const float* __restrict__ Wr3,
                                                 const float* __restrict__ Wr4) {
    extern __shared__ float sm[];
    float* sWr1 = sm + OFF_WR1;
    float* sWr2 = sm + OFF_WR2;
    float* sWr3 = sm + OFF_WR3;
    float* sWr4 = sm + OFF_WR4;
    float* sHa  = sm + OFF_HA;
    float* sHb  = sm + OFF_HB;
    float* sTPW = sm + OFF_TPW;
    float* sEF  = sm + OFF_EF;
    float* sEA  = sm + OFF_EA;
    int*   sSrc = (int*)(sm + OFF_SRC);
    int*   sDst = (int*)(sm + OFF_DST);
    const int t = threadIdx.x;
    for (int i = t; i < 512;   i += 256) sWr1[i] = Wr1[i];
    for (int i = t; i < 4096;  i += 256) { sWr2[i] = Wr2[i]; sWr3[i] = Wr3[i]; }
    for (int i = t; i < 16384; i += 256) sWr4[i] = Wr4[i];
    const int te = t >> 3, tc = t & 7;
    const int e0l = 2 * te, e1l = 2 * te + 1, cb = tc * 8;
    const int q = t & 3, el = t >> 2;

    for (int tile = blockIdx.x; tile < N_EDGES / 64; tile += gridDim.x) {
        const int eg = tile * 64;
        __syncthreads();
        for (int i = t; i < 512; i += 256) sEF[i] = ef[(size_t)eg * 8 + i];
        sEA[t] = ea[(size_t)eg * 4 + t];
        if (t < 64)       sSrc[t] = src[eg + t];
        else if (t < 128) sDst[t - 64] = dst[eg + t - 64];
        __syncthreads();
        gemm_tile<8, 64, true>(sEF, 8, sWr1, 0, sHa, ST_H, 0, C_R1, e0l, e1l, cb);
        __syncthreads();
        gemm_tile<64, 64, true>(sHa, ST_H, sWr2, 0, sHb, ST_H, 0, C_R, e0l, e1l, cb);
        __syncthreads();
        gemm_tile<64, 64, true>(sHb, ST_H, sWr3, 0, sHa, ST_H, 0, C_R, e0l, e1l, cb);
        __syncthreads();
        #pragma unroll
        for (int cc = 0; cc < 4; cc++)
            gemm_tile<64, 256, false>(sHa, ST_H, sWr4, cc * 64, sTPW, ST_TPW, cc * 64,
                                      C_R, e0l, e1l, cb);
        __syncthreads();
        {
            const int srcn = sSrc[el], dstn = sDst[el];
            const float sh0 = sEA[el * 4 + 0];
            const float a1 = sEA[el * 4 + 1], a2 = sEA[el * 4 + 2], a3 = sEA[el * 4 + 3];
            const float* xrow = g_x + (size_t)srcn * 256;
            float*       mrow = g_m + (size_t)dstn * 512;
            const float* tpw  = sTPW + el * ST_TPW;
            #pragma unroll
            for (int c = 0; c < 4; c++) {
                const int u0 = q * 16 + c * 4;
                const float4 s4 = *(const float4*)(xrow + u0);
                const float4 va = *(const float4*)(xrow + 64 + u0 * 3);
                const float4 vb = *(const float4*)(xrow + 64 + u0 * 3 + 4);
                const float4 vc = *(const float4*)(xrow + 64 + u0 * 3 + 8);
                const float4 t0 = *(const float4*)(tpw + u0);
                const float4 t1 = *(const float4*)(tpw + 64 + u0);
                const float4 t2 = *(const float4*)(tpw + 128 + u0);
                const float4 t3 = *(const float4*)(tpw + 192 + u0);
                float vv[12] = {va.x,va.y,va.z,va.w, vb.x,vb.y,vb.z,vb.w, vc.x,vc.y,vc.z,vc.w};
                float ss[4] = {s4.x, s4.y, s4.z, s4.w};
                float q0[4] = {t0.x, t0.y, t0.z, t0.w};
                float q1[4] = {t1.x, t1.y, t1.z, t1.w};
                float q2[4] = {t2.x, t2.y, t2.z, t2.w};
                float q3[4] = {t3.x, t3.y, t3.z, t3.w};
                float p0[4], p3[4], p1[12], p2[12];
                #pragma unroll
                for (int j = 0; j < 4; j++) {
                    p0[j] = q0[j] * ss[j] * sh0;
                    float dv = vv[j*3]*a1 + vv[j*3+1]*a2 + vv[j*3+2]*a3;
                    p3[j] = q3[j] * dv * INV_SQRT3;
                    float ts = q1[j] * ss[j];
                    p1[j*3+0] = ts*a1; p1[j*3+1] = ts*a2; p1[j*3+2] = ts*a3;
                    float tv = q2[j] * sh0;
                    p2[j*3+0] = tv*vv[j*3]; p2[j*3+1] = tv*vv[j*3+1]; p2[j*3+2] = tv*vv[j*3+2];
                }
                red_add_v4(mrow + u0,      p0[0], p0[1], p0[2], p0[3]);
                red_add_v4(mrow + 64 + u0, p3[0], p3[1], p3[2], p3[3]);
                red_add_v4(mrow + 128 + u0*3,     p1[0], p1[1], p1[2],  p1[3]);
                red_add_v4(mrow + 128 + u0*3 + 4, p1[4], p1[5], p1[6],  p1[7]);
                red_add_v4(mrow + 128 + u0*3 + 8, p1[8], p1[9], p1[10], p1[11]);
                red_add_v4(mrow + 320 + u0*3,     p2[0], p2[1], p2[2],  p2[3]);
                red_add_v4(mrow + 320 + u0*3 + 4, p2[4], p2[5], p2[6],  p2[7]);
                red_add_v4(mrow + 320 + u0*3 + 8, p2[8], p2[9], p2[10], p2[11]);
            }
        }
    }
}

// ==== K2: node output (4 nodes/block): y = m@W_lin, z = skip contraction ====
#define OFF2_WL0 0
#define OFF2_WL1 8192
#define OFF2_M   16384
#define OFF2_Y   18432
#define OFF2_A   19456
#define K2_SMEM_FLOATS (OFF2_A + 64)

__global__ __launch_bounds__(256, 2) void k_node_out(const float* __restrict__ na,
                                                     const float* __restrict__ Wl0,
                                                     const float* __restrict__ Wl1,
                                                     float* __restrict__ out) {
    extern __shared__ float sm[];
    float* sWl0 = sm + OFF2_WL0;
    float* sWl1 = sm + OFF2_WL1;
    float* sM   = sm + OFF2_M;
    float* sY   = sm + OFF2_Y;
    float* sA   = sm + OFF2_A;
    const int t = threadIdx.x;
    const int n0 = blockIdx.x * 4;
    for (int i = t; i < 8192; i += 256) { sWl0[i] = Wl0[i]; sWl1[i] = Wl1[i]; }
    for (int i = t; i < 2048; i += 256) sM[i] = g_m[(size_t)n0 * 512 + i];
    if (t < 40) sA[(t / 10) * 16 + (t % 10)] = na[(size_t)n0 * 10 + t];
    __syncthreads();
    const int nl = t >> 6, u = t & 63;
    const float* m0 = sM + nl * 512;
    const float* m1 = m0 + 128;
    float y0 = 0.f, yx = 0.f, yy = 0.f, yz = 0.f;
    #pragma unroll 4
    for (int v = 0; v < 128; v++) {
        float w0 = sWl0[v * 64 + u], w1 = sWl1[v * 64 + u];
        y0 += m0[v] * w0;
        yx += m1[v*3+0] * w1; yy += m1[v*3+1] * w1; yz += m1[v*3+2] * w1;
    }
    float* yr = sY + nl * 256;
    yr[u]       = y0 * C_LIN;
    yr[64 + u]  = yx * C_LIN;
    yr[128 + u] = yy * C_LIN;
    yr[192 + u] = yz * C_LIN;
    __syncthreads();
    float a[10];
    #pragma unroll
    for (int w = 0; w < 10; w++) a[w] = sA[nl * 16 + w];
    float z0 = 0.f, zx = 0.f, zy = 0.f, zz = 0.f;
    #pragma unroll 4
    for (int v = 0; v < 64; v++) {
        const float* p0 = g_wt0 + v * 640 + u;
        const float* p1 = g_wt1 + v * 640 + u;
        float g0 = 0.f, g1 = 0.f;
        #pragma unroll
        for (int w = 0; w < 10; w++) { g0 += a[w] * p0[w * 64]; g1 += a[w] * p1[w * 64]; }
        z0 += yr[v] * g0;
        zx += yr[64 + v] * g1; zy += yr[128 + v] * g1; zz += yr[192 + v] * g1;
    }
    float* o = out + (size_t)(n0 + nl) * 256;
    o[u] = z0 * C_SKIP;
    o[64 + u*3 + 0] = zx * C_SKIP;
    o[64 + u*3 + 1] = zy * C_SKIP;
    o[64 + u*3 + 2] = zz * C_SKIP;
}

extern "C" void kernel_launch(void* const* d_in, const int* in_sizes, int n_in,
                              void* d_out, int out_size) {
    const float* nf  = (const float*)d_in[0];
    const float* na  = (const float*)d_in[1];
    const float* ef  = (const float*)d_in[2];
    const float* ea  = (const float*)d_in[3];
    const int*   src = (const int*)d_in[4];
    const int*   dst = (const int*)d_in[5];
    const float* Wu0 = (const float*)d_in[6];
    const float* Wu1 = (const float*)d_in[7];
    const float* Wr1 = (const float*)d_in[8];
    const float* Wr2 = (const float*)d_in[9];
    const float* Wr3 = (const float*)d_in[10];
    const float* Wr4 = (const float*)d_in[11];
    const float* Wl0 = (const float*)d_in[12];
    const float* Wl1 = (const float*)d_in[13];
    const float* Ws0 = (const float*)d_in[14];
    const float* Ws1 = (const float*)d_in[15];
    float* out = (float*)d_out;

    cudaFuncSetAttribute(k_edge, cudaFuncAttributeMaxDynamicSharedMemorySize,
                         K1_SMEM_FLOATS * 4);
    cudaFuncSetAttribute(k_node_out, cudaFuncAttributeMaxDynamicSharedMemorySize,
                         K2_SMEM_FLOATS * 4);

    void* gm_ptr = nullptr;
    cudaGetSymbolAddress(&gm_ptr, g_m);
    cudaMemsetAsync(gm_ptr, 0, sizeof(float) * (size_t)N_NODES * 512, 0);

    k_prep<<<640, 64>>>(Ws0, Ws1);
    k_node_up<<<N_NODES / 8, 256>>>(nf, Wu0, Wu1);
    k_edge<<<148, 256, K1_SMEM_FLOATS * 4>>>(ef, ea, src, dst, Wr1, Wr2, Wr3, Wr4);
    k_node_out<<<N_NODES / 4, 256, K2_SMEM_FLOATS * 4>>>(na, Wl0, Wl1, out);
}

// round 4
// speedup vs baseline: 1.2590x; 1.2590x over previous
#include <cuda_runtime.h>
#include <cstdint>
#include <cstddef>

#define N_NODES 32768
#define N_EDGES 524288

// ---- scratch (device globals; allocations forbidden) ----
__device__ float g_x[(size_t)N_NODES * 256];   // [0:64]=x0, [64+u*3+i]=x1[u][i]
__device__ float g_m[(size_t)N_NODES * 512];   // [0:128]=m0, [128+v*3+i]=m1[v][i]
__device__ float g_wt0[64 * 64 * 12];          // [v][u][w] padded w:10->12
__device__ float g_wt1[64 * 64 * 12];

#define C_UP      0.125f
#define C_R1      0.35355339059327373f
#define C_R       0.125f
#define C_LIN     0.00552427172801990f
#define C_SKIP    0.03952847075210474f
#define INV_SQRT3 0.5773502691896258f

__device__ __forceinline__ float silu_f(float x) {
    return __fdividef(x, 1.0f + __expf(-x));
}
__device__ __forceinline__ void red_add_v4(float* a, float x, float y, float z, float w) {
    asm volatile("red.global.add.v4.f32 [%0], {%1,%2,%3,%4};"
                 :: "l"(a), "f"(x), "f"(y), "f"(z), "f"(w) : "memory");
}

// ==== K_prep: W_skip (64,64,10)[u,v,w] -> [v][u][12] (w-padded) ====
__global__ void k_prep(const float* __restrict__ Ws0, const float* __restrict__ Ws1) {
    int idx = blockIdx.x * 256 + threadIdx.x;   // 0 .. 49151
    int v = idx / 768;
    int r = idx % 768;
    int u = r / 12, w = r % 12;
    float a = 0.f, b = 0.f;
    if (w < 10) {
        a = Ws0[u * 640 + v * 10 + w];
        b = Ws1[u * 640 + v * 10 + w];
    }
    g_wt0[idx] = a;
    g_wt1[idx] = b;
}

// ==== K0: node up-projection (8 nodes/block) ====
__global__ __launch_bounds__(256) void k_node_up(const float* __restrict__ nf,
                                                 const float* __restrict__ Wu0,
                                                 const float* __restrict__ Wu1) {
    __shared__ float sW0[4096], sW1[4096], sIn[2048];
    const int t = threadIdx.x;
    for (int i = t; i < 4096; i += 256) { sW0[i] = Wu0[i]; sW1[i] = Wu1[i]; }
    const int n0 = blockIdx.x * 8;
    for (int i = t; i < 2048; i += 256) sIn[i] = nf[(size_t)n0 * 256 + i];
    __syncthreads();
    const int j = t >> 6, u = t & 63;
    const int off0 = (j == 0) ? 0 : (63 + j);
    const int st = (j == 0) ? 1 : 3;
    const float* W = (j == 0) ? sW0 : sW1;
    const int oo = (j == 0) ? u : (64 + u * 3 + (j - 1));
    for (int c = 0; c < 2; c++) {
        float acc[4] = {0.f, 0.f, 0.f, 0.f};
        #pragma unroll 8
        for (int v = 0; v < 64; v++) {
            float w = W[v * 64 + u];
            #pragma unroll
            for (int r = 0; r < 4; r++)
                acc[r] += sIn[(c * 4 + r) * 256 + off0 + v * st] * w;
        }
        #pragma unroll
        for (int r = 0; r < 4; r++)
            g_x[(size_t)(n0 + c * 4 + r) * 256 + oo] = acc[r] * C_UP;
    }
}

// ==== K1: persistent edge kernel, 64 edges/tile, fused layer4+message ====
#define ST_H 68
#define OFF_WR1 0
#define OFF_WR2 512
#define OFF_WR3 4608
#define OFF_HA  8704
#define OFF_HB  (OFF_HA + 64*ST_H)
#define OFF_EF  (OFF_HB + 64*ST_H)
#define OFF_EA  (OFF_EF + 512)
#define OFF_SRC (OFF_EA + 256)
#define OFF_DST (OFF_SRC + 64)
#define K1_SMEM_FLOATS (OFF_DST + 64)

template<int K, bool SILU>
__device__ __forceinline__ void gemm_tile(const float* __restrict__ A, int astride,
                                          const float* __restrict__ B,
                                          float* __restrict__ O,
                                          float scale, int e0l, int e1l, int cb) {
    float acc[2][8];
    #pragma unroll
    for (int r = 0; r < 2; r++)
        #pragma unroll
        for (int j = 0; j < 8; j++) acc[r][j] = 0.f;
    #pragma unroll 8
    for (int k = 0; k < K; k++) {
        float a0 = A[e0l * astride + k];
        float a1 = A[e1l * astride + k];
        const float4 b0 = *(const float4*)(B + k * 64 + cb);
        const float4 b1 = *(const float4*)(B + k * 64 + cb + 4);
        acc[0][0] += a0*b0.x; acc[0][1] += a0*b0.y; acc[0][2] += a0*b0.z; acc[0][3] += a0*b0.w;
        acc[0][4] += a0*b1.x; acc[0][5] += a0*b1.y; acc[0][6] += a0*b1.z; acc[0][7] += a0*b1.w;
        acc[1][0] += a1*b0.x; acc[1][1] += a1*b0.y; acc[1][2] += a1*b0.z; acc[1][3] += a1*b0.w;
        acc[1][4] += a1*b1.x; acc[1][5] += a1*b1.y; acc[1][6] += a1*b1.z; acc[1][7] += a1*b1.w;
    }
    #pragma unroll
    for (int r = 0; r < 2; r++) {
        const int e = r ? e1l : e0l;
        float v[8];
        #pragma unroll
        for (int j = 0; j < 8; j++) {
            float x = acc[r][j] * scale;
            v[j] = SILU ? silu_f(x) : x;
        }
        float* op = O + e * ST_H + cb;
        *(float4*)(op)     = make_float4(v[0], v[1], v[2], v[3]);
        *(float4*)(op + 4) = make_float4(v[4], v[5], v[6], v[7]);
    }
}

// layer-4 partial: acc[e][j] for one 64-column chunk cc, B streamed from global (L1)
__device__ __forceinline__ void l4_acc(const float* __restrict__ sHa,
                                       const float* __restrict__ Wr4,
                                       int e0l, int e1l, int cb, int cc,
                                       float (&acc)[2][8]) {
    #pragma unroll
    for (int r = 0; r < 2; r++)
        #pragma unroll
        for (int j = 0; j < 8; j++) acc[r][j] = 0.f;
    const float* B = Wr4 + cc * 64 + cb;
    #pragma unroll 8
    for (int k = 0; k < 64; k++) {
        float a0 = sHa[e0l * ST_H + k];
        float a1 = sHa[e1l * ST_H + k];
        const float4 b0 = __ldg((const float4*)(B + (size_t)k * 256));
        const float4 b1 = __ldg((const float4*)(B + (size_t)k * 256 + 4));
        acc[0][0] += a0*b0.x; acc[0][1] += a0*b0.y; acc[0][2] += a0*b0.z; acc[0][3] += a0*b0.w;
        acc[0][4] += a0*b1.x; acc[0][5] += a0*b1.y; acc[0][6] += a0*b1.z; acc[0][7] += a0*b1.w;
        acc[1][0] += a1*b0.x; acc[1][1] += a1*b0.y; acc[1][2] += a1*b0.z; acc[1][3] += a1*b0.w;
        acc[1][4] += a1*b1.x; acc[1][5] += a1*b1.y; acc[1][6] += a1*b1.z; acc[1][7] += a1*b1.w;
    }
    #pragma unroll
    for (int r = 0; r < 2; r++)
        #pragma unroll
        for (int j = 0; j < 8; j++) acc[r][j] *= C_R;
}

__global__ __launch_bounds__(256, 2) void k_edge(const float* __restrict__ ef,
                                                 const float* __restrict__ ea,
                                                 const int* __restrict__ src,
                                                 const int* __restrict__ dst,
                                                 const float* __restrict__ Wr1,
                                                 const float* __restrict__ Wr2,
                                                 const float* __restrict__ Wr3,
                                                 const float* __restrict__ Wr4) {
    extern __shared__ float sm[];
    float* sWr1 = sm + OFF_WR1;
    float* sWr2 = sm + OFF_WR2;
    float* sWr3 = sm + OFF_WR3;
    float* sHa  = sm + OFF_HA;
    float* sHb  = sm + OFF_HB;
    float* sEF  = sm + OFF_EF;
    float* sEA  = sm + OFF_EA;
    int*   sSrc = (int*)(sm + OFF_SRC);
    int*   sDst = (int*)(sm + OFF_DST);
    const int t = threadIdx.x;
    for (int i = t; i < 512;  i += 256) sWr1[i] = Wr1[i];
    for (int i = t; i < 4096; i += 256) { sWr2[i] = Wr2[i]; sWr3[i] = Wr3[i]; }
    const int te = t >> 3, tc = t & 7;
    const int e0l = 2 * te, e1l = 2 * te + 1, cb = tc * 8;

    for (int tile = blockIdx.x; tile < N_EDGES / 64; tile += gridDim.x) {
        const int eg = tile * 64;
        __syncthreads();
        for (int i = t; i < 512; i += 256) sEF[i] = ef[(size_t)eg * 8 + i];
        sEA[t] = ea[(size_t)eg * 4 + t];
        if (t < 64)       sSrc[t] = src[eg + t];
        else if (t < 128) sDst[t - 64] = dst[eg + t - 64];
        __syncthreads();
        gemm_tile<8,  true>(sEF, 8,    sWr1, sHa, C_R1, e0l, e1l, cb);
        __syncthreads();
        gemm_tile<64, true>(sHa, ST_H, sWr2, sHb, C_R,  e0l, e1l, cb);
        __syncthreads();
        gemm_tile<64, true>(sHb, ST_H, sWr3, sHa, C_R,  e0l, e1l, cb);
        __syncthreads();

        // ---- fused layer-4 + messages ----
        const int sn[2] = {sSrc[e0l], sSrc[e1l]};
        const int dn[2] = {sDst[e0l], sDst[e1l]};
        const float* xr0 = g_x + (size_t)sn[0] * 256;
        const float* xr1 = g_x + (size_t)sn[1] * 256;
        float* mr0 = g_m + (size_t)dn[0] * 512;
        float* mr1 = g_m + (size_t)dn[1] * 512;
        float sh0[2] = {sEA[e0l*4+0], sEA[e1l*4+0]};
        float a1v[2] = {sEA[e0l*4+1], sEA[e1l*4+1]};
        float a2v[2] = {sEA[e0l*4+2], sEA[e1l*4+2]};
        float a3v[2] = {sEA[e0l*4+3], sEA[e1l*4+3]};

        float s[2][8];
        {
            float4 p = *(const float4*)(xr0 + cb);
            float4 q = *(const float4*)(xr0 + cb + 4);
            s[0][0]=p.x; s[0][1]=p.y; s[0][2]=p.z; s[0][3]=p.w;
            s[0][4]=q.x; s[0][5]=q.y; s[0][6]=q.z; s[0][7]=q.w;
            p = *(const float4*)(xr1 + cb);
            q = *(const float4*)(xr1 + cb + 4);
            s[1][0]=p.x; s[1][1]=p.y; s[1][2]=p.z; s[1][3]=p.w;
            s[1][4]=q.x; s[1][5]=q.y; s[1][6]=q.z; s[1][7]=q.w;
        }

        float acc[2][8];
        // cc=0: p0 -> m0[0:64]
        l4_acc(sHa, Wr4, e0l, e1l, cb, 0, acc);
        #pragma unroll
        for (int e = 0; e < 2; e++) {
            float* mr = e ? mr1 : mr0;
            red_add_v4(mr + cb,
                       acc[e][0]*s[e][0]*sh0[e], acc[e][1]*s[e][1]*sh0[e],
                       acc[e][2]*s[e][2]*sh0[e], acc[e][3]*s[e][3]*sh0[e]);
            red_add_v4(mr + cb + 4,
                       acc[e][4]*s[e][4]*sh0[e], acc[e][5]*s[e][5]*sh0[e],
                       acc[e][6]*s[e][6]*sh0[e], acc[e][7]*s[e][7]*sh0[e]);
        }
        // cc=1: p1 -> m1 rows [0:64] -> mrow[128 + u*3 + i]
        l4_acc(sHa, Wr4, e0l, e1l, cb, 1, acc);
        #pragma unroll
        for (int e = 0; e < 2; e++) {
            float* mr = e ? mr1 : mr0;
            float p[24];
            #pragma unroll
            for (int j = 0; j < 8; j++) {
                float ts = acc[e][j] * s[e][j];
                p[j*3+0] = ts * a1v[e];
                p[j*3+1] = ts * a2v[e];
                p[j*3+2] = ts * a3v[e];
            }
            float* b = mr + 128 + cb * 3;
            #pragma unroll
            for (int r = 0; r < 6; r++)
                red_add_v4(b + r*4, p[r*4], p[r*4+1], p[r*4+2], p[r*4+3]);
        }
        // gather v (x1) chunks
        float vv[2][24];
        #pragma unroll
        for (int i = 0; i < 6; i++) {
            float4 p = *(const float4*)(xr0 + 64 + cb*3 + i*4);
            vv[0][i*4+0]=p.x; vv[0][i*4+1]=p.y; vv[0][i*4+2]=p.z; vv[0][i*4+3]=p.w;
            float4 q = *(const float4*)(xr1 + 64 + cb*3 + i*4);
            vv[1][i*4+0]=q.x; vv[1][i*4+1]=q.y; vv[1][i*4+2]=q.z; vv[1][i*4+3]=q.w;
        }
        // cc=2: p2 -> m1 rows [64:128] -> mrow[320 + u*3 + i]
        l4_acc(sHa, Wr4, e0l, e1l, cb, 2, acc);
        #pragma unroll
        for (int e = 0; e < 2; e++) {
            float* mr = e ? mr1 : mr0;
            float p[24];
            #pragma unroll
            for (int j = 0; j < 8; j++) {
                float tv = acc[e][j] * sh0[e];
                p[j*3+0] = tv * vv[e][j*3+0];
                p[j*3+1] = tv * vv[e][j*3+1];
                p[j*3+2] = tv * vv[e][j*3+2];
            }
            float* b = mr + 320 + cb * 3;
            #pragma unroll
            for (int r = 0; r < 6; r++)
                red_add_v4(b + r*4, p[r*4], p[r*4+1], p[r*4+2], p[r*4+3]);
        }
        // cc=3: p3 -> m0[64:128]
        l4_acc(sHa, Wr4, e0l, e1l, cb, 3, acc);
        #pragma unroll
        for (int e = 0; e < 2; e++) {
            float* mr = e ? mr1 : mr0;
            float p[8];
            #pragma unroll
            for (int j = 0; j < 8; j++) {
                float dv = vv[e][j*3+0]*a1v[e] + vv[e][j*3+1]*a2v[e] + vv[e][j*3+2]*a3v[e];
                p[j] = acc[e][j] * dv * INV_SQRT3;
            }
            red_add_v4(mr + 64 + cb,     p[0], p[1], p[2], p[3]);
            red_add_v4(mr + 64 + cb + 4, p[4], p[5], p[6], p[7]);
        }
    }
}

// ==== K2: node output, 16 nodes/block ====
#define NOB 16
#define O2_WL0 0
#define O2_WL1 8192
#define O2_M   16384
#define O2_Y   24576
#define O2_A   28672
#define K2_SMEM_FLOATS (O2_A + 192)

__global__ __launch_bounds__(256, 2) void k_node_out(const float* __restrict__ na,
                                                     const float* __restrict__ Wl0,
                                                     const float* __restrict__ Wl1,
                                                     float* __restrict__ out) {
    extern __shared__ float sm[];
    float* sWl0 = sm + O2_WL0;
    float* sWl1 = sm + O2_WL1;
    float* sWt  = sm;                 // phase-B reuse (12288 floats)
    float* sM   = sm + O2_M;
    float* sY   = sm + O2_Y;
    float* sA   = sm + O2_A;
    const int t = threadIdx.x;
    const int n0 = blockIdx.x * NOB;
    for (int i = t; i < 8192; i += 256) { sWl0[i] = Wl0[i]; sWl1[i] = Wl1[i]; }
    for (int i = t; i < NOB * 512; i += 256) sM[i] = g_m[(size_t)n0 * 512 + i];
    for (int i = t; i < NOB * 12; i += 256) {
        int n = i / 12, w = i % 12;
        sA[i] = (w < 10) ? na[(size_t)(n0 + n) * 10 + w] : 0.f;
    }
    __syncthreads();
    const int n4 = t >> 6, u = t & 63;

    // ---- phase A: y = m @ W_lin ----
    float y[16];
    #pragma unroll
    for (int i = 0; i < 16; i++) y[i] = 0.f;
    #pragma unroll 4
    for (int v = 0; v < 128; v++) {
        float w0 = sWl0[v * 64 + u], w1 = sWl1[v * 64 + u];
        #pragma unroll
        for (int ns = 0; ns < 4; ns++) {
            const float* m = sM + (ns * 4 + n4) * 512;
            y[ns*4+0] += m[v] * w0;
            y[ns*4+1] += m[128 + v*3 + 0] * w1;
            y[ns*4+2] += m[128 + v*3 + 1] * w1;
            y[ns*4+3] += m[128 + v*3 + 2] * w1;
        }
    }
    #pragma unroll
    for (int ns = 0; ns < 4; ns++) {
        float* yb = sY + (ns * 4 + n4) * 256;
        yb[u]       = y[ns*4+0] * C_LIN;
        yb[64 + u]  = y[ns*4+1] * C_LIN;
        yb[128 + u] = y[ns*4+2] * C_LIN;
        yb[192 + u] = y[ns*4+3] * C_LIN;
    }
    float areg[40];
    #pragma unroll
    for (int ns = 0; ns < 4; ns++)
        #pragma unroll
        for (int w = 0; w < 10; w++)
            areg[ns*10 + w] = sA[(ns*4 + n4) * 12 + w];

    // ---- phase B: z = y . (a . W_skip), W_skip streamed via smem ----
    float z[16];
    #pragma unroll
    for (int i = 0; i < 16; i++) z[i] = 0.f;
    for (int vc = 0; vc < 8; vc++) {
        __syncthreads();
        const int v0 = vc * 8;
        const float4* g0p = (const float4*)(g_wt0 + (size_t)v0 * 768);
        const float4* g1p = (const float4*)(g_wt1 + (size_t)v0 * 768);
        float4* d0 = (float4*)sWt;
        float4* d1 = (float4*)(sWt + 6144);
        for (int i = t; i < 1536; i += 256) { d0[i] = g0p[i]; d1[i] = g1p[i]; }
        __syncthreads();
        #pragma unroll
        for (int v = 0; v < 8; v++) {
            const float* w0p = sWt + (v * 64 + u) * 12;
            const float* w1p = sWt + 6144 + (v * 64 + u) * 12;
            float4 wa0 = *(const float4*)(w0p);
            float4 wa1 = *(const float4*)(w0p + 4);
            float4 wa2 = *(const float4*)(w0p + 8);
            float4 wb0 = *(const float4*)(w1p);
            float4 wb1 = *(const float4*)(w1p + 4);
            float4 wb2 = *(const float4*)(w1p + 8);
            #pragma unroll
            for (int ns = 0; ns < 4; ns++) {
                const float* a = areg + ns * 10;
                float g0 = a[0]*wa0.x + a[1]*wa0.y + a[2]*wa0.z + a[3]*wa0.w
                         + a[4]*wa1.x + a[5]*wa1.y + a[6]*wa1.z + a[7]*wa1.w
                         + a[8]*wa2.x + a[9]*wa2.y;
                float g1 = a[0]*wb0.x + a[1]*wb0.y + a[2]*wb0.z + a[3]*wb0.w
                         + a[4]*wb1.x + a[5]*wb1.y + a[6]*wb1.z + a[7]*wb1.w
                         + a[8]*wb2.x + a[9]*wb2.y;
                const float* yp = sY + (ns * 4 + n4) * 256 + v0 + v;
                z[ns*4+0] += yp[0]   * g0;
                z[ns*4+1] += yp[64]  * g1;
                z[ns*4+2] += yp[128] * g1;
                z[ns*4+3] += yp[192] * g1;
            }
        }
    }
    #pragma unroll
    for (int ns = 0; ns < 4; ns++) {
        float* o = out + (size_t)(n0 + ns * 4 + n4) * 256;
        o[u]            = z[ns*4+0] * C_SKIP;
        o[64 + u*3 + 0] = z[ns*4+1] * C_SKIP;
        o[64 + u*3 + 1] = z[ns*4+2] * C_SKIP;
        o[64 + u*3 + 2] = z[ns*4+3] * C_SKIP;
    }
}

extern "C" void kernel_launch(void* const* d_in, const int* in_sizes, int n_in,
                              void* d_out, int out_size) {
    const float* nf  = (const float*)d_in[0];
    const float* na  = (const float*)d_in[1];
    const float* ef  = (const float*)d_in[2];
    const float* ea  = (const float*)d_in[3];
    const int*   src = (const int*)d_in[4];
    const int*   dst = (const int*)d_in[5];
    const float* Wu0 = (const float*)d_in[6];
    const float* Wu1 = (const float*)d_in[7];
    const float* Wr1 = (const float*)d_in[8];
    const float* Wr2 = (const float*)d_in[9];
    const float* Wr3 = (const float*)d_in[10];
    const float* Wr4 = (const float*)d_in[11];
    const float* Wl0 = (const float*)d_in[12];
    const float* Wl1 = (const float*)d_in[13];
    const float* Ws0 = (const float*)d_in[14];
    const float* Ws1 = (const float*)d_in[15];
    float* out = (float*)d_out;

    cudaFuncSetAttribute(k_edge, cudaFuncAttributeMaxDynamicSharedMemorySize,
                         K1_SMEM_FLOATS * 4);
    cudaFuncSetAttribute(k_node_out, cudaFuncAttributeMaxDynamicSharedMemorySize,
                         K2_SMEM_FLOATS * 4);

    void* gm_ptr = nullptr;
    cudaGetSymbolAddress(&gm_ptr, g_m);
    cudaMemsetAsync(gm_ptr, 0, sizeof(float) * (size_t)N_NODES * 512, 0);

    k_prep<<<192, 256>>>(Ws0, Ws1);
    k_node_up<<<N_NODES / 8, 256>>>(nf, Wu0, Wu1);
    k_edge<<<296, 256, K1_SMEM_FLOATS * 4>>>(ef, ea, src, dst, Wr1, Wr2, Wr3, Wr4);
    k_node_out<<<N_NODES / NOB, 256, K2_SMEM_FLOATS * 4>>>(na, Wl0, Wl1, out);
}